// round 9
// baseline (speedup 1.0000x reference)
#include <cuda_runtime.h>
#include <cuda_bf16.h>
#include <cstdint>

#define BSZ   262144
#define IND   128
#define HIDN  256
#define MT    128
#define NBLK  (BSZ / MT)            // 2048

#define WSTR  136                   // padded row stride in bf16 elems (17x16B chunks)
#define PLANE (128 * WSTR * 2)      // 34816 B: one [128 x 128] bf16 plane (padded)
#define GRPB  (2 * PLANE)           // 69632 B: hi+lo planes of one weight group

// ---- dynamic SMEM layout ----
#define SM_A    0                   // A hi | A lo (2 planes) = 69632 B
#define SM_W    (2 * PLANE)         // 2 buffers x GRPB       = 139264 B
#define SM_LAM  (SM_W + 2 * GRPB)   // lam_re[256] lam_im[256] = 2048 B
#define SMEM_SZ (SM_LAM + 2048)     // 210944 B

// Weight images in padded layout: [group g][plane hi/lo][row n][col k]
// group order: g0 = re cols 0-127, g1 = im 0-127, g2 = re 128-255, g3 = im 128-255
__device__ __align__(256) unsigned char g_W[4 * GRPB];
__device__ float g_lam[2 * HIDN];   // re[256] | im[256]

static __device__ __forceinline__ uint32_t s32(const void* p) {
    uint32_t r;
    asm("{ .reg .u64 t; cvta.to.shared.u64 t, %1; cvt.u32.u64 %0, t; }" : "=r"(r) : "l"(p));
    return r;
}
static __device__ __forceinline__ void ldsm4(uint32_t* r, uint32_t a) {
    asm volatile("ldmatrix.sync.aligned.m8n8.x4.shared.b16 {%0,%1,%2,%3}, [%4];"
                 : "=r"(r[0]), "=r"(r[1]), "=r"(r[2]), "=r"(r[3]) : "r"(a));
}
static __device__ __forceinline__ void mma16816(float* d, const uint32_t* a, const uint32_t* b) {
    asm volatile(
        "mma.sync.aligned.m16n8k16.row.col.f32.bf16.bf16.f32 "
        "{%0,%1,%2,%3}, {%4,%5,%6,%7}, {%8,%9}, {%0,%1,%2,%3};"
        : "+f"(d[0]), "+f"(d[1]), "+f"(d[2]), "+f"(d[3])
        : "r"(a[0]), "r"(a[1]), "r"(a[2]), "r"(a[3]), "r"(b[0]), "r"(b[1]));
}
static __device__ __forceinline__ void cpa16(uint32_t dst, const void* src) {
    asm volatile("cp.async.cg.shared.global [%0], [%1], 16;" :: "r"(dst), "l"(src));
}

// ---------------- prep: lambda + bf16 hi/lo weight images ----------------
__global__ void lru_prep(const float* __restrict__ nu_log, const float* __restrict__ theta_log,
                         const float* __restrict__ B_real, const float* __restrict__ B_img,
                         const float* __restrict__ gamma_log) {
    int idx = blockIdx.x * 256 + threadIdx.x;   // 65536 = 4 * 128 * 128
    if (blockIdx.x == 0 && threadIdx.x < HIDN) {
        int h = threadIdx.x;
        float mag = expf(-expf(nu_log[h]));
        float th  = expf(theta_log[h]);
        g_lam[h]        = mag * cosf(th);
        g_lam[HIDN + h] = mag * sinf(th);
    }
    int g = idx >> 14;          // group
    int r = (idx >> 7) & 127;   // n-row within group
    int k = idx & 127;
    int oi = g & 1;             // 0 = real part of B, 1 = imag
    int h = ((g >> 1) << 7) + r;
    const float* Bm = oi ? B_img : B_real;
    float w = expf(gamma_log[h]) * Bm[h * IND + k];
    __nv_bfloat16 hi = __float2bfloat16(w);
    __nv_bfloat16 lo = __float2bfloat16(w - __bfloat162float(hi));
    size_t base = (size_t)g * GRPB + (size_t)(r * WSTR + k) * 2;
    *(__nv_bfloat16*)(g_W + base)         = hi;
    *(__nv_bfloat16*)(g_W + base + PLANE) = lo;
}

// ---------------- main ----------------
__global__ void __launch_bounds__(256, 1)
lru_main(const float* __restrict__ inp, const float* __restrict__ hre,
         const float* __restrict__ him, float* __restrict__ out) {
    extern __shared__ __align__(128) char smem[];
    const uint32_t sb = s32(smem);
    const int tid  = threadIdx.x;
    const int lane = tid & 31;
    const int wid  = tid >> 5;
    const int wm   = wid & 3;     // M-warp: rows wm*32 .. +32
    const int wn   = wid >> 2;    // N-warp: cols wn*64 .. +64 within group

    // kick off cp.async of weight groups 0 and 1 (whole group = flat 69632 B)
    #pragma unroll
    for (int gq = 0; gq < 2; gq++) {
        uint32_t d = sb + SM_W + gq * GRPB;
        const unsigned char* src = g_W + (size_t)gq * GRPB;
        #pragma unroll
        for (int i = 0; i < 17; i++) {          // 4352 chunks of 16 B
            int ch = i * 256 + tid;
            cpa16(d + ch * 16, src + (size_t)ch * 16);
        }
        asm volatile("cp.async.commit_group;" ::: "memory");
    }

    // A tile: fp32 -> bf16 hi/lo into padded SMEM planes
    {
        const float4* A4 = (const float4*)(inp + (size_t)blockIdx.x * (MT * IND));
        #pragma unroll
        for (int i = 0; i < 16; i++) {
            int f = i * 256 + tid;              // 4096 float4 in tile
            int r = f >> 5;
            int c = (f & 31) << 2;
            float4 v = A4[f];
            float hx = __bfloat162float(__float2bfloat16(v.x));
            float hy = __bfloat162float(__float2bfloat16(v.y));
            float hz = __bfloat162float(__float2bfloat16(v.z));
            float hw = __bfloat162float(__float2bfloat16(v.w));
            __nv_bfloat162 H01 = __floats2bfloat162_rn(v.x, v.y);
            __nv_bfloat162 H23 = __floats2bfloat162_rn(v.z, v.w);
            __nv_bfloat162 L01 = __floats2bfloat162_rn(v.x - hx, v.y - hy);
            __nv_bfloat162 L23 = __floats2bfloat162_rn(v.z - hz, v.w - hw);
            uint2 H, L;
            H.x = *reinterpret_cast<uint32_t*>(&H01);
            H.y = *reinterpret_cast<uint32_t*>(&H23);
            L.x = *reinterpret_cast<uint32_t*>(&L01);
            L.y = *reinterpret_cast<uint32_t*>(&L23);
            uint32_t off = (uint32_t)(r * WSTR + c) * 2;
            *(uint2*)(smem + SM_A + off)         = H;
            *(uint2*)(smem + SM_A + PLANE + off) = L;
        }
        float* lam_s = (float*)(smem + SM_LAM);
        lam_s[tid]       = g_lam[tid];
        lam_s[tid + 256] = g_lam[tid + 256];
    }
    __syncthreads();

    // per-lane ldmatrix byte offsets (within a plane)
    const uint32_t a_lane = (uint32_t)(((lane & 15) * WSTR + (lane >> 4) * 8) * 2);
    const uint32_t b_lane = (uint32_t)((((lane & 7) + ((lane >> 4) << 3)) * WSTR
                                       + (((lane >> 3) & 1) * 8)) * 2);

    for (int g = 0; g < 4; g++) {
        if (g < 3) asm volatile("cp.async.wait_group 1;" ::: "memory");
        else       asm volatile("cp.async.wait_group 0;" ::: "memory");
        __syncthreads();

        const uint32_t wb = sb + SM_W + (uint32_t)(g & 1) * GRPB;
        const uint32_t ab = sb + SM_A;

        float acc[2][8][4] = {};
        #pragma unroll
        for (int ks = 0; ks < 8; ks++) {
            uint32_t ah[2][4], al[2][4];
            #pragma unroll
            for (int mi = 0; mi < 2; mi++) {
                uint32_t aoff = (uint32_t)(((wm * 32 + mi * 16) * WSTR + ks * 16) * 2) + a_lane;
                ldsm4(ah[mi], ab + aoff);
                ldsm4(al[mi], ab + PLANE + aoff);
            }
            uint32_t bh[8][2], bl[8][2];
            #pragma unroll
            for (int nj = 0; nj < 4; nj++) {
                uint32_t boff = (uint32_t)(((wn * 64 + nj * 16) * WSTR + ks * 16) * 2) + b_lane;
                ldsm4(&bh[nj * 2][0], wb + boff);            // fills bh[2nj], bh[2nj+1]
                ldsm4(&bl[nj * 2][0], wb + PLANE + boff);
            }
            #pragma unroll
            for (int mi = 0; mi < 2; mi++)
                #pragma unroll
                for (int nt = 0; nt < 8; nt++) {
                    mma16816(acc[mi][nt], ah[mi], bh[nt]);   // Ah * Wh
                    mma16816(acc[mi][nt], al[mi], bh[nt]);   // Al * Wh
                    mma16816(acc[mi][nt], ah[mi], bl[nt]);   // Ah * Wl
                }
        }
        __syncthreads();

        // prefetch group g+2 into the buffer we just finished reading
        if (g < 2) {
            uint32_t d = sb + SM_W + (uint32_t)(g & 1) * GRPB;
            const unsigned char* src = g_W + (size_t)(g + 2) * GRPB;
            #pragma unroll
            for (int i = 0; i < 17; i++) {
                int ch = i * 256 + tid;
                cpa16(d + ch * 16, src + (size_t)ch * 16);
            }
            asm volatile("cp.async.commit_group;" ::: "memory");
        }

        // epilogue: out = lam (*) h + proj  (complex), fused, float2 stores
        const int oi = g & 1;
        const int hb = ((g >> 1) << 7) + wn * 64;
        const float* lamr = (const float*)(smem + SM_LAM) + hb;
        const float* lami = (const float*)(smem + SM_LAM) + 256 + hb;
        float2 lrv[8], liv[8];
        #pragma unroll
        for (int nt = 0; nt < 8; nt++) {
            int c = nt * 8 + (lane & 3) * 2;
            lrv[nt] = *(const float2*)(lamr + c);
            liv[nt] = *(const float2*)(lami + c);
        }
        #pragma unroll
        for (int mi = 0; mi < 2; mi++) {
            #pragma unroll
            for (int rr = 0; rr < 2; rr++) {
                size_t row = (size_t)blockIdx.x * MT + (size_t)(wm * 32 + mi * 16 + rr * 8 + (lane >> 2));
                const float* hrp = hre + row * HIDN + hb;
                const float* hip = him + row * HIDN + hb;
                float* op = out + (size_t)oi * ((size_t)BSZ * HIDN) + row * HIDN + hb;
                #pragma unroll
                for (int nt = 0; nt < 8; nt++) {
                    int c = nt * 8 + (lane & 3) * 2;
                    float2 hrv = *(const float2*)(hrp + c);
                    float2 hiv = *(const float2*)(hip + c);
                    float p0 = acc[mi][nt][rr * 2 + 0];
                    float p1 = acc[mi][nt][rr * 2 + 1];
                    float2 o;
                    if (oi == 0) {
                        o.x = fmaf(lrv[nt].x, hrv.x, fmaf(-liv[nt].x, hiv.x, p0));
                        o.y = fmaf(lrv[nt].y, hrv.y, fmaf(-liv[nt].y, hiv.y, p1));
                    } else {
                        o.x = fmaf(lrv[nt].x, hiv.x, fmaf(liv[nt].x, hrv.x, p0));
                        o.y = fmaf(lrv[nt].y, hiv.y, fmaf(liv[nt].y, hrv.y, p1));
                    }
                    *(float2*)(op + c) = o;
                }
            }
        }
    }
}

extern "C" void kernel_launch(void* const* d_in, const int* in_sizes, int n_in,
                              void* d_out, int out_size) {
    const float* inp   = (const float*)d_in[0];
    const float* h_re  = (const float*)d_in[1];
    const float* h_im  = (const float*)d_in[2];
    const float* nu    = (const float*)d_in[3];
    const float* theta = (const float*)d_in[4];
    const float* Br    = (const float*)d_in[5];
    const float* Bi    = (const float*)d_in[6];
    const float* gl    = (const float*)d_in[7];

    cudaFuncSetAttribute(lru_main, cudaFuncAttributeMaxDynamicSharedMemorySize, SMEM_SZ);
    lru_prep<<<256, 256>>>(nu, theta, Br, Bi, gl);
    lru_main<<<NBLK, 256, SMEM_SZ>>>(inp, h_re, h_im, (float*)d_out);
}

// round 11
// speedup vs baseline: 1.1303x; 1.1303x over previous
#include <cuda_runtime.h>
#include <cuda_bf16.h>
#include <cstdint>

#define BSZ   262144
#define IND   128
#define HIDN  256
#define MT    64
#define NBLK  (BSZ / MT)            // 4096

#define WSTR   136                  // padded row stride in bf16 elems
#define APLANE (64 * WSTR * 2)      // 17408 B: A [64 x 128] bf16 plane (padded)
#define WPLANE (128 * WSTR * 2)     // 34816 B: W [128 x 128] bf16 plane (padded)
#define GRPB   (2 * WPLANE)         // 69632 B: hi+lo planes of one weight group

// ---- dynamic SMEM layout (per CTA: 106496 B -> 2 CTAs/SM) ----
#define SM_A    0                   // A hi | A lo = 34816 B
#define SM_W    (2 * APLANE)        // one weight group (hi|lo) = 69632 B
#define SM_LAM  (SM_W + GRPB)       // lam_re[256] lam_im[256] = 2048 B
#define SMEM_SZ (SM_LAM + 2048)     // 106496 B

// Weight images: [group][hi|lo][row n][col k], padded stride WSTR.
// groups: g0 = re cols 0-127, g1 = im 0-127, g2 = re 128-255, g3 = im 128-255
__device__ __align__(256) unsigned char g_W[4 * GRPB];
__device__ float g_lam[2 * HIDN];

static __device__ __forceinline__ uint32_t s32(const void* p) {
    uint32_t r;
    asm("{ .reg .u64 t; cvta.to.shared.u64 t, %1; cvt.u32.u64 %0, t; }" : "=r"(r) : "l"(p));
    return r;
}
static __device__ __forceinline__ void ldsm4(uint32_t* r, uint32_t a) {
    asm volatile("ldmatrix.sync.aligned.m8n8.x4.shared.b16 {%0,%1,%2,%3}, [%4];"
                 : "=r"(r[0]), "=r"(r[1]), "=r"(r[2]), "=r"(r[3]) : "r"(a));
}
static __device__ __forceinline__ void mma16816(float* d, const uint32_t* a, const uint32_t* b) {
    asm volatile(
        "mma.sync.aligned.m16n8k16.row.col.f32.bf16.bf16.f32 "
        "{%0,%1,%2,%3}, {%4,%5,%6,%7}, {%8,%9}, {%0,%1,%2,%3};"
        : "+f"(d[0]), "+f"(d[1]), "+f"(d[2]), "+f"(d[3])
        : "r"(a[0]), "r"(a[1]), "r"(a[2]), "r"(a[3]), "r"(b[0]), "r"(b[1]));
}
static __device__ __forceinline__ void cpa16(uint32_t dst, const void* src) {
    asm volatile("cp.async.cg.shared.global [%0], [%1], 16;" :: "r"(dst), "l"(src));
}

// ---------------- prep: lambda + bf16 hi/lo weight images ----------------
__global__ void lru_prep(const float* __restrict__ nu_log, const float* __restrict__ theta_log,
                         const float* __restrict__ B_real, const float* __restrict__ B_img,
                         const float* __restrict__ gamma_log) {
    int idx = blockIdx.x * 256 + threadIdx.x;   // 65536 = 4 * 128 * 128
    if (blockIdx.x == 0 && threadIdx.x < HIDN) {
        int h = threadIdx.x;
        float mag = expf(-expf(nu_log[h]));
        float th  = expf(theta_log[h]);
        g_lam[h]        = mag * cosf(th);
        g_lam[HIDN + h] = mag * sinf(th);
    }
    int g = idx >> 14;
    int r = (idx >> 7) & 127;
    int k = idx & 127;
    int oi = g & 1;
    int h = ((g >> 1) << 7) + r;
    const float* Bm = oi ? B_img : B_real;
    float w = expf(gamma_log[h]) * Bm[h * IND + k];
    __nv_bfloat16 hi = __float2bfloat16(w);
    __nv_bfloat16 lo = __float2bfloat16(w - __bfloat162float(hi));
    size_t base = (size_t)g * GRPB + (size_t)(r * WSTR + k) * 2;
    *(__nv_bfloat16*)(g_W + base)          = hi;
    *(__nv_bfloat16*)(g_W + base + WPLANE) = lo;
}

// ---------------- main ----------------
__global__ void __launch_bounds__(256, 2)
lru_main(const float* __restrict__ inp, const float* __restrict__ hre,
         const float* __restrict__ him, float* __restrict__ out) {
    extern __shared__ __align__(128) char smem[];
    const uint32_t sb = s32(smem);
    const int tid  = threadIdx.x;
    const int lane = tid & 31;
    const int wid  = tid >> 5;
    const int wm   = wid & 1;     // M-warp: rows wm*32 .. +32
    const int wn   = wid >> 1;    // N-warp: cols wn*32 .. +32 of group

    // kick off weight group 0 (flat 69632 B, 4352 x 16B chunks)
    {
        uint32_t d = sb + SM_W;
        const unsigned char* src = g_W;
        #pragma unroll
        for (int i = 0; i < 17; i++) {
            int ch = i * 256 + tid;
            cpa16(d + ch * 16, src + (size_t)ch * 16);
        }
        asm volatile("cp.async.commit_group;" ::: "memory");
    }

    // A tile: fp32 -> bf16 hi/lo into padded SMEM planes (64 x 128)
    {
        const float4* A4 = (const float4*)(inp + (size_t)blockIdx.x * (MT * IND));
        #pragma unroll
        for (int i = 0; i < 8; i++) {
            int f = i * 256 + tid;              // 2048 float4
            int r = f >> 5;
            int c = (f & 31) << 2;
            float4 v = A4[f];
            float hx = __bfloat162float(__float2bfloat16(v.x));
            float hy = __bfloat162float(__float2bfloat16(v.y));
            float hz = __bfloat162float(__float2bfloat16(v.z));
            float hw = __bfloat162float(__float2bfloat16(v.w));
            __nv_bfloat162 H01 = __floats2bfloat162_rn(v.x, v.y);
            __nv_bfloat162 H23 = __floats2bfloat162_rn(v.z, v.w);
            __nv_bfloat162 L01 = __floats2bfloat162_rn(v.x - hx, v.y - hy);
            __nv_bfloat162 L23 = __floats2bfloat162_rn(v.z - hz, v.w - hw);
            uint2 H, L;
            H.x = *reinterpret_cast<uint32_t*>(&H01);
            H.y = *reinterpret_cast<uint32_t*>(&H23);
            L.x = *reinterpret_cast<uint32_t*>(&L01);
            L.y = *reinterpret_cast<uint32_t*>(&L23);
            uint32_t off = (uint32_t)(r * WSTR + c) * 2;
            *(uint2*)(smem + SM_A + off)          = H;
            *(uint2*)(smem + SM_A + APLANE + off) = L;
        }
        float* lam_s = (float*)(smem + SM_LAM);
        lam_s[tid]       = g_lam[tid];
        lam_s[tid + 256] = g_lam[tid + 256];
    }

    const uint32_t a_lane = (uint32_t)(((lane & 15) * WSTR + (lane >> 4) * 8) * 2);
    const uint32_t b_lane = (uint32_t)((((lane & 7) + ((lane >> 4) << 3)) * WSTR
                                       + (((lane >> 3) & 1) * 8)) * 2);
    const uint32_t ab = sb + SM_A;
    const uint32_t wb = sb + SM_W;

    for (int g = 0; g < 4; g++) {
        asm volatile("cp.async.wait_group 0;" ::: "memory");
        __syncthreads();

        float acc[2][4][4] = {};
        #pragma unroll
        for (int ks = 0; ks < 8; ks++) {
            uint32_t ah[2][4], al[2][4];
            #pragma unroll
            for (int mi = 0; mi < 2; mi++) {
                uint32_t aoff = (uint32_t)(((wm * 32 + mi * 16) * WSTR + ks * 16) * 2) + a_lane;
                ldsm4(ah[mi], ab + aoff);
                ldsm4(al[mi], ab + APLANE + aoff);
            }
            uint32_t bh[4][2], bl[4][2];
            #pragma unroll
            for (int nj = 0; nj < 2; nj++) {
                uint32_t boff = (uint32_t)(((wn * 32 + nj * 16) * WSTR + ks * 16) * 2) + b_lane;
                ldsm4(&bh[nj * 2][0], wb + boff);
                ldsm4(&bl[nj * 2][0], wb + WPLANE + boff);
            }
            #pragma unroll
            for (int mi = 0; mi < 2; mi++)
                #pragma unroll
                for (int nt = 0; nt < 4; nt++) {
                    mma16816(acc[mi][nt], ah[mi], bh[nt]);   // Ah * Wh
                    mma16816(acc[mi][nt], al[mi], bh[nt]);   // Al * Wh
                    mma16816(acc[mi][nt], ah[mi], bl[nt]);   // Ah * Wl
                }
        }
        __syncthreads();   // all warps done reading W buffer

        // stream next group's weights under the epilogue's DRAM latency
        if (g < 3) {
            const unsigned char* src = g_W + (size_t)(g + 1) * GRPB;
            #pragma unroll
            for (int i = 0; i < 17; i++) {
                int ch = i * 256 + tid;
                cpa16(wb + ch * 16, src + (size_t)ch * 16);
            }
            asm volatile("cp.async.commit_group;" ::: "memory");
        }

        // epilogue: out = lam (*) h + proj, fused, float2 coalesced
        const int oi = g & 1;
        const int hb = ((g >> 1) << 7) + wn * 32;
        const float* lamr = (const float*)(smem + SM_LAM) + hb;
        const float* lami = (const float*)(smem + SM_LAM) + 256 + hb;
        float2 lrv[4], liv[4];
        #pragma unroll
        for (int nt = 0; nt < 4; nt++) {
            int c = nt * 8 + (lane & 3) * 2;
            lrv[nt] = *(const float2*)(lamr + c);
            liv[nt] = *(const float2*)(lami + c);
        }
        #pragma unroll
        for (int mi = 0; mi < 2; mi++) {
            #pragma unroll
            for (int rr = 0; rr < 2; rr++) {
                size_t row = (size_t)blockIdx.x * MT
                           + (size_t)(wm * 32 + mi * 16 + rr * 8 + (lane >> 2));
                const float* hrp = hre + row * HIDN + hb;
                const float* hip = him + row * HIDN + hb;
                float* op = out + (size_t)oi * ((size_t)BSZ * HIDN) + row * HIDN + hb;
                float2 hrv[4], hiv[4];
                #pragma unroll
                for (int nt = 0; nt < 4; nt++) {
                    int c = nt * 8 + (lane & 3) * 2;
                    hrv[nt] = *(const float2*)(hrp + c);
                    hiv[nt] = *(const float2*)(hip + c);
                }
                #pragma unroll
                for (int nt = 0; nt < 4; nt++) {
                    int c = nt * 8 + (lane & 3) * 2;
                    float p0 = acc[mi][nt][rr * 2 + 0];
                    float p1 = acc[mi][nt][rr * 2 + 1];
                    float2 o;
                    if (oi == 0) {
                        o.x = fmaf(lrv[nt].x, hrv[nt].x, fmaf(-liv[nt].x, hiv[nt].x, p0));
                        o.y = fmaf(lrv[nt].y, hrv[nt].y, fmaf(-liv[nt].y, hiv[nt].y, p1));
                    } else {
                        o.x = fmaf(lrv[nt].x, hiv[nt].x, fmaf(liv[nt].x, hrv[nt].x, p0));
                        o.y = fmaf(lrv[nt].y, hiv[nt].y, fmaf(liv[nt].y, hrv[nt].y, p1));
                    }
                    *(float2*)(op + c) = o;
                }
            }
        }
    }
}

extern "C" void kernel_launch(void* const* d_in, const int* in_sizes, int n_in,
                              void* d_out, int out_size) {
    const float* inp   = (const float*)d_in[0];
    const float* h_re  = (const float*)d_in[1];
    const float* h_im  = (const float*)d_in[2];
    const float* nu    = (const float*)d_in[3];
    const float* theta = (const float*)d_in[4];
    const float* Br    = (const float*)d_in[5];
    const float* Bi    = (const float*)d_in[6];
    const float* gl    = (const float*)d_in[7];

    cudaFuncSetAttribute(lru_main, cudaFuncAttributeMaxDynamicSharedMemorySize, SMEM_SZ);
    lru_prep<<<256, 256>>>(nu, theta, Br, Bi, gl);
    lru_main<<<NBLK, 256, SMEM_SZ>>>(inp, h_re, h_im, (float*)d_out);
}

// round 12
// speedup vs baseline: 1.5788x; 1.3968x over previous
#include <cuda_runtime.h>
#include <cuda_bf16.h>
#include <cstdint>

#define BSZ   262144
#define IND   128
#define HIDN  256
#define MT    64
#define NBLK  (BSZ / MT)            // 4096

#define WSTR   136                  // padded row stride in bf16 elems
#define APLANE (64 * WSTR * 2)      // 17408 B: A [64 x 128] bf16 plane (padded)
#define WPLANE (128 * WSTR * 2)     // 34816 B: W [128 x 128] bf16 plane (padded)
#define GRPB   (2 * WPLANE)         // 69632 B: hi+lo planes of one weight group

// ---- dynamic SMEM layout (per CTA: 106496 B -> 2 CTAs/SM) ----
#define SM_A    0                   // A hi | A lo = 34816 B
#define SM_W    (2 * APLANE)        // one weight group (hi|lo) = 69632 B
#define SM_LAM  (SM_W + GRPB)       // lam_re[256] lam_im[256] = 2048 B
#define SMEM_SZ (SM_LAM + 2048)     // 106496 B

// Weight images: [group][hi|lo][row n][col k], padded stride WSTR.
// groups: g0 = re cols 0-127, g1 = im 0-127, g2 = re 128-255, g3 = im 128-255
__device__ __align__(256) unsigned char g_W[4 * GRPB];
__device__ float g_lam[2 * HIDN];

static __device__ __forceinline__ uint32_t s32(const void* p) {
    uint32_t r;
    asm("{ .reg .u64 t; cvta.to.shared.u64 t, %1; cvt.u32.u64 %0, t; }" : "=r"(r) : "l"(p));
    return r;
}
static __device__ __forceinline__ void ldsm4(uint32_t* r, uint32_t a) {
    asm volatile("ldmatrix.sync.aligned.m8n8.x4.shared.b16 {%0,%1,%2,%3}, [%4];"
                 : "=r"(r[0]), "=r"(r[1]), "=r"(r[2]), "=r"(r[3]) : "r"(a));
}
static __device__ __forceinline__ void mma16816(float* d, const uint32_t* a, const uint32_t* b) {
    asm volatile(
        "mma.sync.aligned.m16n8k16.row.col.f32.bf16.bf16.f32 "
        "{%0,%1,%2,%3}, {%4,%5,%6,%7}, {%8,%9}, {%0,%1,%2,%3};"
        : "+f"(d[0]), "+f"(d[1]), "+f"(d[2]), "+f"(d[3])
        : "r"(a[0]), "r"(a[1]), "r"(a[2]), "r"(a[3]), "r"(b[0]), "r"(b[1]));
}
static __device__ __forceinline__ void cpa16(uint32_t dst, const void* src) {
    asm volatile("cp.async.cg.shared.global [%0], [%1], 16;" :: "r"(dst), "l"(src));
}

// ---------------- prep: lambda + bf16 hi/lo weight images ----------------
__global__ void lru_prep(const float* __restrict__ nu_log, const float* __restrict__ theta_log,
                         const float* __restrict__ B_real, const float* __restrict__ B_img,
                         const float* __restrict__ gamma_log) {
    int idx = blockIdx.x * 256 + threadIdx.x;   // 65536 = 4 * 128 * 128
    if (blockIdx.x == 0 && threadIdx.x < HIDN) {
        int h = threadIdx.x;
        float mag = expf(-expf(nu_log[h]));
        float th  = expf(theta_log[h]);
        g_lam[h]        = mag * cosf(th);
        g_lam[HIDN + h] = mag * sinf(th);
    }
    int g = idx >> 14;
    int r = (idx >> 7) & 127;
    int k = idx & 127;
    int oi = g & 1;
    int h = ((g >> 1) << 7) + r;
    const float* Bm = oi ? B_img : B_real;
    float w = expf(gamma_log[h]) * Bm[h * IND + k];
    __nv_bfloat16 hi = __float2bfloat16(w);
    __nv_bfloat16 lo = __float2bfloat16(w - __bfloat162float(hi));
    size_t base = (size_t)g * GRPB + (size_t)(r * WSTR + k) * 2;
    *(__nv_bfloat16*)(g_W + base)          = hi;
    *(__nv_bfloat16*)(g_W + base + WPLANE) = lo;
}

// ---------------- main ----------------
__global__ void __launch_bounds__(256, 2)
lru_main(const float* __restrict__ inp, const float* __restrict__ hre,
         const float* __restrict__ him, float* __restrict__ out) {
    extern __shared__ __align__(128) char smem[];
    const uint32_t sb = s32(smem);
    const int tid  = threadIdx.x;
    const int lane = tid & 31;
    const int wid  = tid >> 5;
    const int wm   = wid & 1;     // M-warp: rows wm*32 .. +32
    const int wn   = wid >> 1;    // N-warp: cols wn*32 .. +32 of group

    // kick off weight group 0 (flat 69632 B, 4352 x 16B chunks)
    {
        uint32_t d = sb + SM_W;
        const unsigned char* src = g_W;
        #pragma unroll
        for (int i = 0; i < 17; i++) {
            int ch = i * 256 + tid;
            cpa16(d + ch * 16, src + (size_t)ch * 16);
        }
        asm volatile("cp.async.commit_group;" ::: "memory");
    }

    // A tile: fp32 -> bf16 hi/lo into padded SMEM planes (64 x 128)
    {
        const float4* A4 = (const float4*)(inp + (size_t)blockIdx.x * (MT * IND));
        #pragma unroll
        for (int i = 0; i < 8; i++) {
            int f = i * 256 + tid;              // 2048 float4
            int r = f >> 5;
            int c = (f & 31) << 2;
            float4 v = A4[f];
            float hx = __bfloat162float(__float2bfloat16(v.x));
            float hy = __bfloat162float(__float2bfloat16(v.y));
            float hz = __bfloat162float(__float2bfloat16(v.z));
            float hw = __bfloat162float(__float2bfloat16(v.w));
            __nv_bfloat162 H01 = __floats2bfloat162_rn(v.x, v.y);
            __nv_bfloat162 H23 = __floats2bfloat162_rn(v.z, v.w);
            __nv_bfloat162 L01 = __floats2bfloat162_rn(v.x - hx, v.y - hy);
            __nv_bfloat162 L23 = __floats2bfloat162_rn(v.z - hz, v.w - hw);
            uint2 H, L;
            H.x = *reinterpret_cast<uint32_t*>(&H01);
            H.y = *reinterpret_cast<uint32_t*>(&H23);
            L.x = *reinterpret_cast<uint32_t*>(&L01);
            L.y = *reinterpret_cast<uint32_t*>(&L23);
            uint32_t off = (uint32_t)(r * WSTR + c) * 2;
            *(uint2*)(smem + SM_A + off)          = H;
            *(uint2*)(smem + SM_A + APLANE + off) = L;
        }
        float* lam_s = (float*)(smem + SM_LAM);
        lam_s[tid]       = g_lam[tid];
        lam_s[tid + 256] = g_lam[tid + 256];
    }

    const uint32_t a_lane = (uint32_t)(((lane & 15) * WSTR + (lane >> 4) * 8) * 2);
    const uint32_t b_lane = (uint32_t)((((lane & 7) + ((lane >> 4) << 3)) * WSTR
                                       + (((lane >> 3) & 1) * 8)) * 2);
    const uint32_t ab = sb + SM_A;
    const uint32_t wb = sb + SM_W;

    for (int g = 0; g < 4; g++) {
        asm volatile("cp.async.wait_group 0;" ::: "memory");
        __syncthreads();

        float acc[2][4][4] = {};
        // double-buffered fragments: [buf][...]
        uint32_t ah[2][2][4], al[2][2][4], bh[2][4][2], bl[2][4][2];

        // fragment loader for one k-step into buffer `buf`
        auto ldfrag = [&](int ks, int buf) {
            #pragma unroll
            for (int mi = 0; mi < 2; mi++) {
                uint32_t aoff = (uint32_t)(((wm * 32 + mi * 16) * WSTR + ks * 16) * 2) + a_lane;
                ldsm4(ah[buf][mi], ab + aoff);
                ldsm4(al[buf][mi], ab + APLANE + aoff);
            }
            #pragma unroll
            for (int nj = 0; nj < 2; nj++) {
                uint32_t boff = (uint32_t)(((wn * 32 + nj * 16) * WSTR + ks * 16) * 2) + b_lane;
                ldsm4(&bh[buf][nj * 2][0], wb + boff);
                ldsm4(&bl[buf][nj * 2][0], wb + WPLANE + boff);
            }
        };

        ldfrag(0, 0);
        #pragma unroll
        for (int ks = 0; ks < 8; ks++) {
            const int cur = ks & 1;
            if (ks < 7) ldfrag(ks + 1, cur ^ 1);   // prefetch next k-step under mmas
            #pragma unroll
            for (int mi = 0; mi < 2; mi++)
                #pragma unroll
                for (int nt = 0; nt < 4; nt++) {
                    mma16816(acc[mi][nt], ah[cur][mi], bh[cur][nt]);   // Ah*Wh
                    mma16816(acc[mi][nt], al[cur][mi], bh[cur][nt]);   // Al*Wh
                    mma16816(acc[mi][nt], ah[cur][mi], bl[cur][nt]);   // Ah*Wl
                }
        }
        __syncthreads();   // all warps done reading W buffer

        // stream next group's weights under the epilogue
        if (g < 3) {
            const unsigned char* src = g_W + (size_t)(g + 1) * GRPB;
            #pragma unroll
            for (int i = 0; i < 17; i++) {
                int ch = i * 256 + tid;
                cpa16(wb + ch * 16, src + (size_t)ch * 16);
            }
            asm volatile("cp.async.commit_group;" ::: "memory");
        }

        // ---- epilogue: hoist ALL h loads first (MLP ~32), then fuse + store ----
        const int oi = g & 1;
        const int hb = ((g >> 1) << 7) + wn * 32;
        const float* lamr = (const float*)(smem + SM_LAM) + hb;
        const float* lami = (const float*)(smem + SM_LAM) + 256 + hb;
        float2 lrv[4], liv[4];
        #pragma unroll
        for (int nt = 0; nt < 4; nt++) {
            int c = nt * 8 + (lane & 3) * 2;
            lrv[nt] = *(const float2*)(lamr + c);
            liv[nt] = *(const float2*)(lami + c);
        }

        const size_t row0 = (size_t)blockIdx.x * MT + (size_t)(wm * 32 + (lane >> 2));
        float2 hrv[2][2][4], hiv[2][2][4];
        #pragma unroll
        for (int mi = 0; mi < 2; mi++)
            #pragma unroll
            for (int rr = 0; rr < 2; rr++) {
                size_t row = row0 + (size_t)(mi * 16 + rr * 8);
                const float* hrp = hre + row * HIDN + hb;
                const float* hip = him + row * HIDN + hb;
                #pragma unroll
                for (int nt = 0; nt < 4; nt++) {
                    int c = nt * 8 + (lane & 3) * 2;
                    hrv[mi][rr][nt] = *(const float2*)(hrp + c);
                    hiv[mi][rr][nt] = *(const float2*)(hip + c);
                }
            }

        #pragma unroll
        for (int mi = 0; mi < 2; mi++)
            #pragma unroll
            for (int rr = 0; rr < 2; rr++) {
                size_t row = row0 + (size_t)(mi * 16 + rr * 8);
                float* op = out + (size_t)oi * ((size_t)BSZ * HIDN) + row * HIDN + hb;
                #pragma unroll
                for (int nt = 0; nt < 4; nt++) {
                    int c = nt * 8 + (lane & 3) * 2;
                    float p0 = acc[mi][nt][rr * 2 + 0];
                    float p1 = acc[mi][nt][rr * 2 + 1];
                    float2 hr2 = hrv[mi][rr][nt], hi2 = hiv[mi][rr][nt];
                    float2 o;
                    if (oi == 0) {
                        o.x = fmaf(lrv[nt].x, hr2.x, fmaf(-liv[nt].x, hi2.x, p0));
                        o.y = fmaf(lrv[nt].y, hr2.y, fmaf(-liv[nt].y, hi2.y, p1));
                    } else {
                        o.x = fmaf(lrv[nt].x, hi2.x, fmaf(liv[nt].x, hr2.x, p0));
                        o.y = fmaf(lrv[nt].y, hi2.y, fmaf(liv[nt].y, hr2.y, p1));
                    }
                    *(float2*)(op + c) = o;
                }
            }
    }
}

extern "C" void kernel_launch(void* const* d_in, const int* in_sizes, int n_in,
                              void* d_out, int out_size) {
    const float* inp   = (const float*)d_in[0];
    const float* h_re  = (const float*)d_in[1];
    const float* h_im  = (const float*)d_in[2];
    const float* nu    = (const float*)d_in[3];
    const float* theta = (const float*)d_in[4];
    const float* Br    = (const float*)d_in[5];
    const float* Bi    = (const float*)d_in[6];
    const float* gl    = (const float*)d_in[7];

    cudaFuncSetAttribute(lru_main, cudaFuncAttributeMaxDynamicSharedMemorySize, SMEM_SZ);
    lru_prep<<<256, 256>>>(nu, theta, Br, Bi, gl);
    lru_main<<<NBLK, 256, SMEM_SZ>>>(inp, h_re, h_im, (float*)d_out);
}